// round 1
// baseline (speedup 1.0000x reference)
#include <cuda_runtime.h>

// Problem constants
#define Bsz  2
#define Sdim 2048
#define Ddim 1024
#define Hn   16
#define HDim 64
#define Mrows (Bsz * Sdim)   // 4096

// Scratch (device globals — no cudaMalloc allowed)
__device__ float g_Q[Bsz * Hn * Sdim * HDim];   // [b,h,s,hd]
__device__ float g_K[Bsz * Hn * Sdim * HDim];
__device__ float g_V[Bsz * Hn * Sdim * HDim];
__device__ float g_ctx[Mrows * Ddim];           // [b*s, d]

// ---------------------------------------------------------------------------
// SGEMM 128x128x8 tile, 256 threads, 8x8 microtile.
// C[M=4096, N=1024] = X @ W ; epilogue scatters into [B,H,S,HD] for Q/K/V.
// ---------------------------------------------------------------------------
__global__ __launch_bounds__(256)
void qkv_gemm(const float* __restrict__ X,
              const float* __restrict__ Wq,
              const float* __restrict__ Wk,
              const float* __restrict__ Wv)
{
    const int K = Ddim, N = Ddim;
    const float* W = (blockIdx.z == 0) ? Wq : (blockIdx.z == 1) ? Wk : Wv;
    float* Out = (blockIdx.z == 0) ? g_Q : (blockIdx.z == 1) ? g_K : g_V;

    __shared__ float As[8][128];
    __shared__ float Bs[8][128];

    const int tid = threadIdx.x;
    const int m0 = blockIdx.y * 128;
    const int n0 = blockIdx.x * 128;

    const int a_row = tid >> 1;         // 0..127
    const int a_col = (tid & 1) * 4;    // 0 or 4
    const int b_row = tid >> 5;         // 0..7
    const int b_col = (tid & 31) * 4;   // 0..124

    const int ty = tid >> 4;            // 0..15
    const int tx = tid & 15;            // 0..15

    float acc[8][8];
#pragma unroll
    for (int i = 0; i < 8; i++)
#pragma unroll
        for (int j = 0; j < 8; j++) acc[i][j] = 0.f;

    for (int k0 = 0; k0 < K; k0 += 8) {
        float4 av = *(const float4*)(X + (size_t)(m0 + a_row) * K + k0 + a_col);
        As[a_col + 0][a_row] = av.x;
        As[a_col + 1][a_row] = av.y;
        As[a_col + 2][a_row] = av.z;
        As[a_col + 3][a_row] = av.w;
        *(float4*)&Bs[b_row][b_col] =
            *(const float4*)(W + (size_t)(k0 + b_row) * N + n0 + b_col);
        __syncthreads();
#pragma unroll
        for (int k = 0; k < 8; k++) {
            float ar[8], br[8];
            *(float4*)(ar)     = *(const float4*)&As[k][ty * 8];
            *(float4*)(ar + 4) = *(const float4*)&As[k][ty * 8 + 4];
            *(float4*)(br)     = *(const float4*)&Bs[k][tx * 8];
            *(float4*)(br + 4) = *(const float4*)&Bs[k][tx * 8 + 4];
#pragma unroll
            for (int i = 0; i < 8; i++)
#pragma unroll
                for (int j = 0; j < 8; j++)
                    acc[i][j] += ar[i] * br[j];
        }
        __syncthreads();
    }

    // Scatter epilogue: row = b*S+s ; col = h*64+hd -> Out[((b*H+h)*S+s)*64+hd]
    const int row0 = m0 + ty * 8;
    const int col0 = n0 + tx * 8;
    const int h = col0 >> 6;            // constant over the thread's 8 cols
    const int hd = col0 & 63;
#pragma unroll
    for (int i = 0; i < 8; i++) {
        int row = row0 + i;
        int b = row >> 11;              // / 2048
        int s = row & 2047;
        float* dst = Out + (((size_t)(b * Hn + h) * Sdim + s) << 6) + hd;
        *(float4*)(dst)     = make_float4(acc[i][0], acc[i][1], acc[i][2], acc[i][3]);
        *(float4*)(dst + 4) = make_float4(acc[i][4], acc[i][5], acc[i][6], acc[i][7]);
    }
}

// ---------------------------------------------------------------------------
// Output projection: out = ctx @ Wo + bo, written to d_out directly.
// ---------------------------------------------------------------------------
__global__ __launch_bounds__(256)
void out_gemm(const float* __restrict__ Wo,
              const float* __restrict__ bo,
              float* __restrict__ out)
{
    const int K = Ddim, N = Ddim;
    const float* A = g_ctx;

    __shared__ float As[8][128];
    __shared__ float Bs[8][128];

    const int tid = threadIdx.x;
    const int m0 = blockIdx.y * 128;
    const int n0 = blockIdx.x * 128;

    const int a_row = tid >> 1;
    const int a_col = (tid & 1) * 4;
    const int b_row = tid >> 5;
    const int b_col = (tid & 31) * 4;

    const int ty = tid >> 4;
    const int tx = tid & 15;

    float acc[8][8];
#pragma unroll
    for (int i = 0; i < 8; i++)
#pragma unroll
        for (int j = 0; j < 8; j++) acc[i][j] = 0.f;

    for (int k0 = 0; k0 < K; k0 += 8) {
        float4 av = *(const float4*)(A + (size_t)(m0 + a_row) * K + k0 + a_col);
        As[a_col + 0][a_row] = av.x;
        As[a_col + 1][a_row] = av.y;
        As[a_col + 2][a_row] = av.z;
        As[a_col + 3][a_row] = av.w;
        *(float4*)&Bs[b_row][b_col] =
            *(const float4*)(Wo + (size_t)(k0 + b_row) * N + n0 + b_col);
        __syncthreads();
#pragma unroll
        for (int k = 0; k < 8; k++) {
            float ar[8], br[8];
            *(float4*)(ar)     = *(const float4*)&As[k][ty * 8];
            *(float4*)(ar + 4) = *(const float4*)&As[k][ty * 8 + 4];
            *(float4*)(br)     = *(const float4*)&Bs[k][tx * 8];
            *(float4*)(br + 4) = *(const float4*)&Bs[k][tx * 8 + 4];
#pragma unroll
            for (int i = 0; i < 8; i++)
#pragma unroll
                for (int j = 0; j < 8; j++)
                    acc[i][j] += ar[i] * br[j];
        }
        __syncthreads();
    }

    const int row0 = m0 + ty * 8;
    const int col0 = n0 + tx * 8;
    float bias[8];
#pragma unroll
    for (int j = 0; j < 8; j++) bias[j] = bo[col0 + j];
#pragma unroll
    for (int i = 0; i < 8; i++) {
        float* dst = out + (size_t)(row0 + i) * N + col0;
        *(float4*)(dst)     = make_float4(acc[i][0] + bias[0], acc[i][1] + bias[1],
                                          acc[i][2] + bias[2], acc[i][3] + bias[3]);
        *(float4*)(dst + 4) = make_float4(acc[i][4] + bias[4], acc[i][5] + bias[5],
                                          acc[i][6] + bias[6], acc[i][7] + bias[7]);
    }
}

// ---------------------------------------------------------------------------
// Flash attention (causal), fp32. 1 thread = 1 query row; 64 threads/block.
// q[64] and o[64] live in registers; K/V tiles (64x64) in smem (broadcast
// reads across the warp). Online softmax in 8-key chunks. Only the diagonal
// tile (k0 == q0) needs masking.
// ---------------------------------------------------------------------------
__global__ __launch_bounds__(64)
void attn_kernel()
{
    const int h = blockIdx.y;
    const int b = blockIdx.z;
    const int q0 = blockIdx.x * 64;
    const int qi = q0 + threadIdx.x;

    const size_t base = ((size_t)(b * Hn + h) * Sdim) * HDim;
    const float* Qp = g_Q + base;
    const float* Kp = g_K + base;
    const float* Vp = g_V + base;

    float q[64];
#pragma unroll
    for (int d = 0; d < 64; d += 4) {
        float4 t = *(const float4*)(Qp + (size_t)qi * 64 + d);
        q[d] = t.x; q[d + 1] = t.y; q[d + 2] = t.z; q[d + 3] = t.w;
    }
    float o[64];
#pragma unroll
    for (int d = 0; d < 64; d++) o[d] = 0.f;
    float m = -1e30f, l = 0.f;

    __shared__ float Ks[64][64];
    __shared__ float Vs[64][64];

    for (int k0 = 0; k0 <= q0; k0 += 64) {
        __syncthreads();   // previous iteration's smem reads complete
#pragma unroll
        for (int i = 0; i < 16; i++) {
            int idx = i * 64 + threadIdx.x;   // 0..1023 float4 slots
            int r = idx >> 4;
            int c = (idx & 15) * 4;
            *(float4*)&Ks[r][c] = *(const float4*)(Kp + (size_t)(k0 + r) * 64 + c);
            *(float4*)&Vs[r][c] = *(const float4*)(Vp + (size_t)(k0 + r) * 64 + c);
        }
        __syncthreads();

        const bool lastTile = (k0 == q0);

        for (int jj = 0; jj < 64; jj += 8) {
            float sarr[8];
#pragma unroll
            for (int u = 0; u < 8; u++) {
                const int j = jj + u;
                float a = 0.f;
                const float4* kr = (const float4*)Ks[j];
#pragma unroll
                for (int d4 = 0; d4 < 16; d4++) {
                    float4 kv = kr[d4];
                    a += q[d4 * 4 + 0] * kv.x;
                    a += q[d4 * 4 + 1] * kv.y;
                    a += q[d4 * 4 + 2] * kv.z;
                    a += q[d4 * 4 + 3] * kv.w;
                }
                bool valid = !lastTile || (j <= (int)threadIdx.x);
                sarr[u] = valid ? a * 0.125f : -1e30f;   // 1/sqrt(64)
            }
            float cmax = sarr[0];
#pragma unroll
            for (int u = 1; u < 8; u++) cmax = fmaxf(cmax, sarr[u]);
            float mnew = fmaxf(m, cmax);
            float scale = __expf(m - mnew);
            float p[8];
            float psum = 0.f;
#pragma unroll
            for (int u = 0; u < 8; u++) { p[u] = __expf(sarr[u] - mnew); psum += p[u]; }
            l = l * scale + psum;
            m = mnew;
#pragma unroll
            for (int d = 0; d < 64; d++) o[d] *= scale;
#pragma unroll
            for (int u = 0; u < 8; u++) {
                const float4* vr = (const float4*)Vs[jj + u];
#pragma unroll
                for (int d4 = 0; d4 < 16; d4++) {
                    float4 vv = vr[d4];
                    o[d4 * 4 + 0] += p[u] * vv.x;
                    o[d4 * 4 + 1] += p[u] * vv.y;
                    o[d4 * 4 + 2] += p[u] * vv.z;
                    o[d4 * 4 + 3] += p[u] * vv.w;
                }
            }
        }
    }

    const float inv = 1.f / l;
    float* op = g_ctx + ((size_t)(b * Sdim + qi)) * Ddim + h * 64;
#pragma unroll
    for (int d = 0; d < 64; d += 4) {
        *(float4*)(op + d) = make_float4(o[d] * inv, o[d + 1] * inv,
                                         o[d + 2] * inv, o[d + 3] * inv);
    }
}

// ---------------------------------------------------------------------------
extern "C" void kernel_launch(void* const* d_in, const int* in_sizes, int n_in,
                              void* d_out, int out_size)
{
    const float* x  = (const float*)d_in[0];
    const float* Wq = (const float*)d_in[1];
    const float* Wk = (const float*)d_in[2];
    const float* Wv = (const float*)d_in[3];
    const float* Wo = (const float*)d_in[4];
    const float* bo = (const float*)d_in[5];
    float* out = (float*)d_out;

    dim3 gQKV(Ddim / 128, Mrows / 128, 3);     // (8, 32, 3)
    qkv_gemm<<<gQKV, 256>>>(x, Wq, Wk, Wv);

    dim3 gAttn(Sdim / 64, Hn, Bsz);            // (32, 16, 2)
    attn_kernel<<<gAttn, 64>>>();

    dim3 gOut(Ddim / 128, Mrows / 128);        // (8, 32)
    out_gemm<<<gOut, 256>>>(Wo, bo, out);
}

// round 3
// speedup vs baseline: 1.5789x; 1.5789x over previous
#include <cuda_runtime.h>
#include <cstdint>

// Problem constants
#define Bsz  2
#define Sdim 2048
#define Ddim 1024
#define Hn   16
#define HDim 64
#define Mrows (Bsz * Sdim)   // 4096

// ---------------------------------------------------------------------------
// Device scratch (no cudaMalloc allowed)
// ---------------------------------------------------------------------------
__device__ float g_Q[Bsz * Hn * Sdim * HDim];   // [b,h,s,hd]
__device__ float g_K[Bsz * Hn * Sdim * HDim];
__device__ float g_V[Bsz * Hn * Sdim * HDim];
__device__ float g_ctx[Mrows * Ddim];           // [b*s, d]
__device__ float g_WT[4 * Ddim * Ddim];         // transposed weights [N][K]: q,k,v,o

// ---------------------------------------------------------------------------
// tf32 helpers (all sm_80-compatible PTX; no tcgen05 — compute_103 target!)
// ---------------------------------------------------------------------------
__device__ __forceinline__ uint32_t to_tf32(float x) {
    uint32_t r;
    asm("cvt.rna.tf32.f32 %0, %1;" : "=r"(r) : "f"(x));
    return r;
}

__device__ __forceinline__ void mma_tf32(float d[4], const uint32_t a[4],
                                         const uint32_t b[2]) {
    asm volatile(
        "mma.sync.aligned.m16n8k8.row.col.f32.tf32.tf32.f32 "
        "{%0,%1,%2,%3}, {%4,%5,%6,%7}, {%8,%9}, {%0,%1,%2,%3};"
        : "+f"(d[0]), "+f"(d[1]), "+f"(d[2]), "+f"(d[3])
        : "r"(a[0]), "r"(a[1]), "r"(a[2]), "r"(a[3]), "r"(b[0]), "r"(b[1]));
}

// ---------------------------------------------------------------------------
// GEMM configuration: C[128,128] tile, 256 thr = 8 warps in 2(M)x4(N),
// warp tile 64x32, K-chunk 32, double-buffered smem, register-staged LDG.
//
// Smem layout is FRAGMENT-ORDER so fragment loads are vector LDS:
//  A: 32 blocks [mt 0..7][ks 0..3], 512B each padded to 528B.
//     element (r', c') of a 16x8 tile: lane l=(r'%8)*4+(c'%4),
//     reg = (r'/8) + 2*(c'/4), at offset l*16 + reg*4.
//  B: 64 blocks [nt 0..15][ks 0..3], 256B each padded to 264B.
//     element (n', k') of an 8x8 tile: lane l=(n'%8)*4+(k'%4), reg=k'/4,
//     at offset l*8 + reg*4.
// ---------------------------------------------------------------------------
#define ABLK 528
#define BBLK 264
#define ABYTES (32 * ABLK)          // 16896
#define BBYTES (64 * BBLK)          // 16896
#define STAGEB (ABYTES + BBYTES)    // 33792
#define GEMM_SMEM (2 * STAGEB)      // 67584
#define NCHUNKS (Ddim / 32)         // 32

__device__ __forceinline__ void run_gemm_tf32(
    const float* __restrict__ A, const float* __restrict__ Bt,
    int m0, int n0, char* smem, float acc[4][4][4])
{
    const int tid = threadIdx.x;
    const int lane = tid & 31;
    const int w = tid >> 5;
    const int wm = w & 1;
    const int wn = w >> 1;

    // Per-thread gmem pointers and smem scatter addresses (constant over chunks)
    const float* agp[4];
    const float* bgp[4];
    int asa[4], bsa[4];
#pragma unroll
    for (int it = 0; it < 4; it++) {
        int idx = it * 256 + tid;
        int r = idx >> 3;         // row 0..127 (A) / n 0..127 (B)
        int c4 = idx & 7;         // float4 col within 32-wide chunk
        agp[it] = A + (size_t)(m0 + r) * Ddim + c4 * 4;
        asa[it] = ((r >> 4) * 4 + (c4 >> 1)) * ABLK
                + (((r >> 3) & 1) + 2 * (c4 & 1)) * 4 + (r & 7) * 64;
        bgp[it] = Bt + (size_t)(n0 + r) * Ddim + c4 * 4;
        bsa[it] = ABYTES + ((r >> 3) * 4 + (c4 >> 1)) * BBLK
                + (c4 & 1) * 4 + (r & 7) * 32;
    }

    float4 av[4], bv[4];
    // Prologue: load chunk 0
#pragma unroll
    for (int it = 0; it < 4; it++) {
        av[it] = *(const float4*)(agp[it]);
        bv[it] = *(const float4*)(bgp[it]);
    }
    // Store chunk 0 -> stage 0
    {
        char* da = smem;
#pragma unroll
        for (int it = 0; it < 4; it++) {
            *(uint32_t*)(da + asa[it] + 0)  = to_tf32(av[it].x);
            *(uint32_t*)(da + asa[it] + 16) = to_tf32(av[it].y);
            *(uint32_t*)(da + asa[it] + 32) = to_tf32(av[it].z);
            *(uint32_t*)(da + asa[it] + 48) = to_tf32(av[it].w);
            *(uint32_t*)(da + bsa[it] + 0)  = to_tf32(bv[it].x);
            *(uint32_t*)(da + bsa[it] + 8)  = to_tf32(bv[it].y);
            *(uint32_t*)(da + bsa[it] + 16) = to_tf32(bv[it].z);
            *(uint32_t*)(da + bsa[it] + 24) = to_tf32(bv[it].w);
        }
    }
    __syncthreads();

    for (int c = 0; c < NCHUNKS; c++) {
        // Issue LDGs for chunk c+1 (fly under the MMAs below)
        if (c + 1 < NCHUNKS) {
            const int ko = (c + 1) * 32;
#pragma unroll
            for (int it = 0; it < 4; it++) {
                av[it] = *(const float4*)(agp[it] + ko);
                bv[it] = *(const float4*)(bgp[it] + ko);
            }
        }
        // Compute chunk c from stage c&1
        const char* sa = smem + (size_t)(c & 1) * STAGEB;
        const char* sb = sa + ABYTES;
#pragma unroll
        for (int ks = 0; ks < 4; ks++) {
            uint4 af[4];
            uint2 bf[4];
#pragma unroll
            for (int i = 0; i < 4; i++)
                af[i] = *(const uint4*)(sa + ((wm * 4 + i) * 4 + ks) * ABLK + lane * 16);
#pragma unroll
            for (int j = 0; j < 4; j++)
                bf[j] = *(const uint2*)(sb + ((wn * 4 + j) * 4 + ks) * BBLK + lane * 8);
#pragma unroll
            for (int i = 0; i < 4; i++)
#pragma unroll
                for (int j = 0; j < 4; j++)
                    mma_tf32(acc[i][j], (const uint32_t*)&af[i], (const uint32_t*)&bf[j]);
        }
        // Store chunk c+1 -> other stage
        if (c + 1 < NCHUNKS) {
            char* da = smem + (size_t)((c + 1) & 1) * STAGEB;
#pragma unroll
            for (int it = 0; it < 4; it++) {
                *(uint32_t*)(da + asa[it] + 0)  = to_tf32(av[it].x);
                *(uint32_t*)(da + asa[it] + 16) = to_tf32(av[it].y);
                *(uint32_t*)(da + asa[it] + 32) = to_tf32(av[it].z);
                *(uint32_t*)(da + asa[it] + 48) = to_tf32(av[it].w);
                *(uint32_t*)(da + bsa[it] + 0)  = to_tf32(bv[it].x);
                *(uint32_t*)(da + bsa[it] + 8)  = to_tf32(bv[it].y);
                *(uint32_t*)(da + bsa[it] + 16) = to_tf32(bv[it].z);
                *(uint32_t*)(da + bsa[it] + 24) = to_tf32(bv[it].w);
            }
            __syncthreads();
        }
    }
}

// ---------------------------------------------------------------------------
// QKV projections: C = X @ Wt^T, scattered to [B,H,S,HD]. grid.z = q/k/v.
// ---------------------------------------------------------------------------
__global__ __launch_bounds__(256)
void qkv_tc(const float* __restrict__ X)
{
    extern __shared__ char smem[];
    const int z = blockIdx.z;
    const float* Bt = g_WT + (size_t)z * Ddim * Ddim;
    float* Out = (z == 0) ? g_Q : (z == 1) ? g_K : g_V;
    const int m0 = blockIdx.y * 128;
    const int n0 = blockIdx.x * 128;

    float acc[4][4][4];
#pragma unroll
    for (int i = 0; i < 4; i++)
#pragma unroll
        for (int j = 0; j < 4; j++)
#pragma unroll
            for (int r = 0; r < 4; r++) acc[i][j][r] = 0.f;

    run_gemm_tf32(X, Bt, m0, n0, smem, acc);

    const int lane = threadIdx.x & 31;
    const int w = threadIdx.x >> 5;
    const int wm = w & 1;
    const int wn = w >> 1;
#pragma unroll
    for (int i = 0; i < 4; i++) {
#pragma unroll
        for (int j = 0; j < 4; j++) {
            const int row = m0 + wm * 64 + i * 16 + (lane >> 2);
            const int col = n0 + wn * 32 + j * 8 + (lane & 3) * 2;
            const int h = col >> 6;
            const int hd = col & 63;
            int b = row >> 11, s = row & 2047;
            *(float2*)(Out + (((size_t)(b * Hn + h) * Sdim + s) << 6) + hd) =
                make_float2(acc[i][j][0], acc[i][j][1]);
            const int r2 = row + 8;
            b = r2 >> 11; s = r2 & 2047;
            *(float2*)(Out + (((size_t)(b * Hn + h) * Sdim + s) << 6) + hd) =
                make_float2(acc[i][j][2], acc[i][j][3]);
        }
    }
}

// ---------------------------------------------------------------------------
// Output projection: out = ctx @ Wo^T + bo
// ---------------------------------------------------------------------------
__global__ __launch_bounds__(256)
void out_tc(const float* __restrict__ bo, float* __restrict__ out)
{
    extern __shared__ char smem[];
    const float* Bt = g_WT + (size_t)3 * Ddim * Ddim;
    const int m0 = blockIdx.y * 128;
    const int n0 = blockIdx.x * 128;

    float acc[4][4][4];
#pragma unroll
    for (int i = 0; i < 4; i++)
#pragma unroll
        for (int j = 0; j < 4; j++)
#pragma unroll
            for (int r = 0; r < 4; r++) acc[i][j][r] = 0.f;

    run_gemm_tf32(g_ctx, Bt, m0, n0, smem, acc);

    const int lane = threadIdx.x & 31;
    const int w = threadIdx.x >> 5;
    const int wm = w & 1;
    const int wn = w >> 1;
#pragma unroll
    for (int i = 0; i < 4; i++) {
#pragma unroll
        for (int j = 0; j < 4; j++) {
            const int row = m0 + wm * 64 + i * 16 + (lane >> 2);
            const int col = n0 + wn * 32 + j * 8 + (lane & 3) * 2;
            const float2 bb = *(const float2*)(bo + col);
            *(float2*)(out + (size_t)row * Ddim + col) =
                make_float2(acc[i][j][0] + bb.x, acc[i][j][1] + bb.y);
            *(float2*)(out + (size_t)(row + 8) * Ddim + col) =
                make_float2(acc[i][j][2] + bb.x, acc[i][j][3] + bb.y);
        }
    }
}

// ---------------------------------------------------------------------------
// Weight transpose: g_WT[z][n][k] = W_z[k][n]
// ---------------------------------------------------------------------------
__global__ __launch_bounds__(256)
void transpose_w(const float* __restrict__ W0, const float* __restrict__ W1,
                 const float* __restrict__ W2, const float* __restrict__ W3)
{
    const float* W = (blockIdx.z == 0) ? W0 : (blockIdx.z == 1) ? W1
                   : (blockIdx.z == 2) ? W2 : W3;
    float* Wt = g_WT + (size_t)blockIdx.z * Ddim * Ddim;
    __shared__ float t[32][33];
    const int tx = threadIdx.x, ty = threadIdx.y;
    const int x = blockIdx.x * 32 + tx;
    const int y0 = blockIdx.y * 32;
#pragma unroll
    for (int j = ty; j < 32; j += 8)
        t[j][tx] = W[(size_t)(y0 + j) * Ddim + x];
    __syncthreads();
    const int x2 = y0 + tx;
    const int y2 = blockIdx.x * 32;
#pragma unroll
    for (int j = ty; j < 32; j += 8)
        Wt[(size_t)(y2 + j) * Ddim + x2] = t[tx][j];
}

// ---------------------------------------------------------------------------
// Flash attention (causal), fp32 SIMT. 1 thread = 1 query row.
// exp2-domain softmax, rescale-skip, split dot-product accumulators.
// ---------------------------------------------------------------------------
__global__ __launch_bounds__(64)
void attn_kernel()
{
    const int h = blockIdx.y;
    const int b = blockIdx.z;
    const int q0 = blockIdx.x * 64;
    const int qi = q0 + threadIdx.x;

    const size_t base = ((size_t)(b * Hn + h) * Sdim) * HDim;
    const float* Qp = g_Q + base;
    const float* Kp = g_K + base;
    const float* Vp = g_V + base;

    const float SCL = 0.125f * 1.4426950408889634f;  // 1/sqrt(64) * log2(e)
    float q[64];
#pragma unroll
    for (int d = 0; d < 64; d += 4) {
        float4 t = *(const float4*)(Qp + (size_t)qi * 64 + d);
        q[d] = t.x * SCL; q[d + 1] = t.y * SCL;
        q[d + 2] = t.z * SCL; q[d + 3] = t.w * SCL;
    }
    float o[64];
#pragma unroll
    for (int d = 0; d < 64; d++) o[d] = 0.f;
    float m = -1e30f, l = 0.f;

    __shared__ float Ks[64][64];
    __shared__ float Vs[64][64];

    for (int k0 = 0; k0 <= q0; k0 += 64) {
        __syncthreads();
#pragma unroll
        for (int i = 0; i < 16; i++) {
            int idx = i * 64 + threadIdx.x;
            int r = idx >> 4;
            int c = (idx & 15) * 4;
            *(float4*)&Ks[r][c] = *(const float4*)(Kp + (size_t)(k0 + r) * 64 + c);
            *(float4*)&Vs[r][c] = *(const float4*)(Vp + (size_t)(k0 + r) * 64 + c);
        }
        __syncthreads();

        const bool lastTile = (k0 == q0);

        for (int jj = 0; jj < 64; jj += 8) {
            float sarr[8];
#pragma unroll
            for (int u = 0; u < 8; u++) {
                const int j = jj + u;
                float a0 = 0.f, a1 = 0.f, a2 = 0.f, a3 = 0.f;
                const float4* kr = (const float4*)Ks[j];
#pragma unroll
                for (int d4 = 0; d4 < 16; d4++) {
                    float4 kv = kr[d4];
                    a0 += q[d4 * 4 + 0] * kv.x;
                    a1 += q[d4 * 4 + 1] * kv.y;
                    a2 += q[d4 * 4 + 2] * kv.z;
                    a3 += q[d4 * 4 + 3] * kv.w;
                }
                float a = (a0 + a1) + (a2 + a3);
                bool valid = !lastTile || (j <= (int)threadIdx.x);
                sarr[u] = valid ? a : -1e30f;
            }
            float cmax = sarr[0];
#pragma unroll
            for (int u = 1; u < 8; u++) cmax = fmaxf(cmax, sarr[u]);
            if (cmax > m) {
                float sc = exp2f(m - cmax);
                l *= sc;
#pragma unroll
                for (int d = 0; d < 64; d++) o[d] *= sc;
                m = cmax;
            }
            float p[8];
            float psum = 0.f;
#pragma unroll
            for (int u = 0; u < 8; u++) { p[u] = exp2f(sarr[u] - m); psum += p[u]; }
            l += psum;
#pragma unroll
            for (int u = 0; u < 8; u++) {
                const float4* vr = (const float4*)Vs[jj + u];
#pragma unroll
                for (int d4 = 0; d4 < 16; d4++) {
                    float4 vv = vr[d4];
                    o[d4 * 4 + 0] += p[u] * vv.x;
                    o[d4 * 4 + 1] += p[u] * vv.y;
                    o[d4 * 4 + 2] += p[u] * vv.z;
                    o[d4 * 4 + 3] += p[u] * vv.w;
                }
            }
        }
    }

    const float inv = 1.f / l;
    float* op = g_ctx + ((size_t)(b * Sdim + qi)) * Ddim + h * 64;
#pragma unroll
    for (int d = 0; d < 64; d += 4) {
        *(float4*)(op + d) = make_float4(o[d] * inv, o[d + 1] * inv,
                                         o[d + 2] * inv, o[d + 3] * inv);
    }
}

// ---------------------------------------------------------------------------
extern "C" void kernel_launch(void* const* d_in, const int* in_sizes, int n_in,
                              void* d_out, int out_size)
{
    const float* x  = (const float*)d_in[0];
    const float* Wq = (const float*)d_in[1];
    const float* Wk = (const float*)d_in[2];
    const float* Wv = (const float*)d_in[3];
    const float* Wo = (const float*)d_in[4];
    const float* bo = (const float*)d_in[5];
    float* out = (float*)d_out;

    cudaFuncSetAttribute(qkv_tc, cudaFuncAttributeMaxDynamicSharedMemorySize, GEMM_SMEM);
    cudaFuncSetAttribute(out_tc, cudaFuncAttributeMaxDynamicSharedMemorySize, GEMM_SMEM);

    dim3 gT(Ddim / 32, Ddim / 32, 4);          // (32, 32, 4)
    transpose_w<<<gT, dim3(32, 8)>>>(Wq, Wk, Wv, Wo);

    dim3 gQKV(Ddim / 128, Mrows / 128, 3);     // (8, 32, 3)
    qkv_tc<<<gQKV, 256, GEMM_SMEM>>>(x);

    dim3 gAttn(Sdim / 64, Hn, Bsz);            // (32, 16, 2)
    attn_kernel<<<gAttn, 64>>>();

    dim3 gOut(Ddim / 128, Mrows / 128);        // (8, 32)
    out_tc<<<gOut, 256, GEMM_SMEM>>>(bo, out);
}

// round 4
// speedup vs baseline: 3.1089x; 1.9690x over previous
#include <cuda_runtime.h>
#include <cstdint>

// Problem constants
#define Bsz  2
#define Sdim 2048
#define Ddim 1024
#define Hn   16
#define HDim 64
#define Mrows (Bsz * Sdim)   // 4096

// ---------------------------------------------------------------------------
// Device scratch (no cudaMalloc allowed)
// ---------------------------------------------------------------------------
__device__ float g_Q[Bsz * Hn * Sdim * HDim];   // [b,h,s,hd]
__device__ float g_K[Bsz * Hn * Sdim * HDim];
__device__ float g_V[Bsz * Hn * Sdim * HDim];
__device__ float g_ctx[Mrows * Ddim];           // [b*s, d]
__device__ float g_WT[4 * Ddim * Ddim];         // transposed weights [N][K]: q,k,v,o

// ---------------------------------------------------------------------------
// tf32 / mma helpers (sm_80-compatible PTX; compute_103 target, no tcgen05)
// ---------------------------------------------------------------------------
__device__ __forceinline__ uint32_t to_tf32(float x) {
    uint32_t r;
    asm("cvt.rna.tf32.f32 %0, %1;" : "=r"(r) : "f"(x));
    return r;
}

__device__ __forceinline__ float ex2(float x) {
    float r;
    asm("ex2.approx.f32 %0, %1;" : "=f"(r) : "f"(x));
    return r;
}

__device__ __forceinline__ void mma_tf32(float d[4], const uint32_t a[4],
                                         const uint32_t b[2]) {
    asm volatile(
        "mma.sync.aligned.m16n8k8.row.col.f32.tf32.tf32.f32 "
        "{%0,%1,%2,%3}, {%4,%5,%6,%7}, {%8,%9}, {%0,%1,%2,%3};"
        : "+f"(d[0]), "+f"(d[1]), "+f"(d[2]), "+f"(d[3])
        : "r"(a[0]), "r"(a[1]), "r"(a[2]), "r"(a[3]), "r"(b[0]), "r"(b[1]));
}

// ---------------------------------------------------------------------------
// Projection GEMM (unchanged from round 3): 128x128 tile, 8 warps (2x4),
// warp tile 64x32, K-chunk 32, double-buffered fragment-order smem.
// ---------------------------------------------------------------------------
#define ABLK 528
#define BBLK 264
#define ABYTES (32 * ABLK)          // 16896
#define BBYTES (64 * BBLK)          // 16896
#define STAGEB (ABYTES + BBYTES)    // 33792
#define GEMM_SMEM (2 * STAGEB)      // 67584
#define NCHUNKS (Ddim / 32)         // 32

__device__ __forceinline__ void run_gemm_tf32(
    const float* __restrict__ A, const float* __restrict__ Bt,
    int m0, int n0, char* smem, float acc[4][4][4])
{
    const int tid = threadIdx.x;
    const int lane = tid & 31;
    const int w = tid >> 5;
    const int wm = w & 1;
    const int wn = w >> 1;

    const float* agp[4];
    const float* bgp[4];
    int asa[4], bsa[4];
#pragma unroll
    for (int it = 0; it < 4; it++) {
        int idx = it * 256 + tid;
        int r = idx >> 3;
        int c4 = idx & 7;
        agp[it] = A + (size_t)(m0 + r) * Ddim + c4 * 4;
        asa[it] = ((r >> 4) * 4 + (c4 >> 1)) * ABLK
                + (((r >> 3) & 1) + 2 * (c4 & 1)) * 4 + (r & 7) * 64;
        bgp[it] = Bt + (size_t)(n0 + r) * Ddim + c4 * 4;
        bsa[it] = ABYTES + ((r >> 3) * 4 + (c4 >> 1)) * BBLK
                + (c4 & 1) * 4 + (r & 7) * 32;
    }

    float4 av[4], bv[4];
#pragma unroll
    for (int it = 0; it < 4; it++) {
        av[it] = *(const float4*)(agp[it]);
        bv[it] = *(const float4*)(bgp[it]);
    }
    {
        char* da = smem;
#pragma unroll
        for (int it = 0; it < 4; it++) {
            *(uint32_t*)(da + asa[it] + 0)  = to_tf32(av[it].x);
            *(uint32_t*)(da + asa[it] + 16) = to_tf32(av[it].y);
            *(uint32_t*)(da + asa[it] + 32) = to_tf32(av[it].z);
            *(uint32_t*)(da + asa[it] + 48) = to_tf32(av[it].w);
            *(uint32_t*)(da + bsa[it] + 0)  = to_tf32(bv[it].x);
            *(uint32_t*)(da + bsa[it] + 8)  = to_tf32(bv[it].y);
            *(uint32_t*)(da + bsa[it] + 16) = to_tf32(bv[it].z);
            *(uint32_t*)(da + bsa[it] + 24) = to_tf32(bv[it].w);
        }
    }
    __syncthreads();

    for (int c = 0; c < NCHUNKS; c++) {
        if (c + 1 < NCHUNKS) {
            const int ko = (c + 1) * 32;
#pragma unroll
            for (int it = 0; it < 4; it++) {
                av[it] = *(const float4*)(agp[it] + ko);
                bv[it] = *(const float4*)(bgp[it] + ko);
            }
        }
        const char* sa = smem + (size_t)(c & 1) * STAGEB;
        const char* sb = sa + ABYTES;
#pragma unroll
        for (int ks = 0; ks < 4; ks++) {
            uint4 af[4];
            uint2 bf[4];
#pragma unroll
            for (int i = 0; i < 4; i++)
                af[i] = *(const uint4*)(sa + ((wm * 4 + i) * 4 + ks) * ABLK + lane * 16);
#pragma unroll
            for (int j = 0; j < 4; j++)
                bf[j] = *(const uint2*)(sb + ((wn * 4 + j) * 4 + ks) * BBLK + lane * 8);
#pragma unroll
            for (int i = 0; i < 4; i++)
#pragma unroll
                for (int j = 0; j < 4; j++)
                    mma_tf32(acc[i][j], (const uint32_t*)&af[i], (const uint32_t*)&bf[j]);
        }
        if (c + 1 < NCHUNKS) {
            char* da = smem + (size_t)((c + 1) & 1) * STAGEB;
#pragma unroll
            for (int it = 0; it < 4; it++) {
                *(uint32_t*)(da + asa[it] + 0)  = to_tf32(av[it].x);
                *(uint32_t*)(da + asa[it] + 16) = to_tf32(av[it].y);
                *(uint32_t*)(da + asa[it] + 32) = to_tf32(av[it].z);
                *(uint32_t*)(da + asa[it] + 48) = to_tf32(av[it].w);
                *(uint32_t*)(da + bsa[it] + 0)  = to_tf32(bv[it].x);
                *(uint32_t*)(da + bsa[it] + 8)  = to_tf32(bv[it].y);
                *(uint32_t*)(da + bsa[it] + 16) = to_tf32(bv[it].z);
                *(uint32_t*)(da + bsa[it] + 24) = to_tf32(bv[it].w);
            }
            __syncthreads();
        }
    }
}

__global__ __launch_bounds__(256)
void qkv_tc(const float* __restrict__ X)
{
    extern __shared__ char smem[];
    const int z = blockIdx.z;
    const float* Bt = g_WT + (size_t)z * Ddim * Ddim;
    float* Out = (z == 0) ? g_Q : (z == 1) ? g_K : g_V;
    const int m0 = blockIdx.y * 128;
    const int n0 = blockIdx.x * 128;

    float acc[4][4][4];
#pragma unroll
    for (int i = 0; i < 4; i++)
#pragma unroll
        for (int j = 0; j < 4; j++)
#pragma unroll
            for (int r = 0; r < 4; r++) acc[i][j][r] = 0.f;

    run_gemm_tf32(X, Bt, m0, n0, smem, acc);

    const int lane = threadIdx.x & 31;
    const int w = threadIdx.x >> 5;
    const int wm = w & 1;
    const int wn = w >> 1;
#pragma unroll
    for (int i = 0; i < 4; i++) {
#pragma unroll
        for (int j = 0; j < 4; j++) {
            const int row = m0 + wm * 64 + i * 16 + (lane >> 2);
            const int col = n0 + wn * 32 + j * 8 + (lane & 3) * 2;
            const int h = col >> 6;
            const int hd = col & 63;
            int b = row >> 11, s = row & 2047;
            *(float2*)(Out + (((size_t)(b * Hn + h) * Sdim + s) << 6) + hd) =
                make_float2(acc[i][j][0], acc[i][j][1]);
            const int r2 = row + 8;
            b = r2 >> 11; s = r2 & 2047;
            *(float2*)(Out + (((size_t)(b * Hn + h) * Sdim + s) << 6) + hd) =
                make_float2(acc[i][j][2], acc[i][j][3]);
        }
    }
}

__global__ __launch_bounds__(256)
void out_tc(const float* __restrict__ bo, float* __restrict__ out)
{
    extern __shared__ char smem[];
    const float* Bt = g_WT + (size_t)3 * Ddim * Ddim;
    const int m0 = blockIdx.y * 128;
    const int n0 = blockIdx.x * 128;

    float acc[4][4][4];
#pragma unroll
    for (int i = 0; i < 4; i++)
#pragma unroll
        for (int j = 0; j < 4; j++)
#pragma unroll
            for (int r = 0; r < 4; r++) acc[i][j][r] = 0.f;

    run_gemm_tf32(g_ctx, Bt, m0, n0, smem, acc);

    const int lane = threadIdx.x & 31;
    const int w = threadIdx.x >> 5;
    const int wm = w & 1;
    const int wn = w >> 1;
#pragma unroll
    for (int i = 0; i < 4; i++) {
#pragma unroll
        for (int j = 0; j < 4; j++) {
            const int row = m0 + wm * 64 + i * 16 + (lane >> 2);
            const int col = n0 + wn * 32 + j * 8 + (lane & 3) * 2;
            const float2 bb = *(const float2*)(bo + col);
            *(float2*)(out + (size_t)row * Ddim + col) =
                make_float2(acc[i][j][0] + bb.x, acc[i][j][1] + bb.y);
            *(float2*)(out + (size_t)(row + 8) * Ddim + col) =
                make_float2(acc[i][j][2] + bb.x, acc[i][j][3] + bb.y);
        }
    }
}

__global__ __launch_bounds__(256)
void transpose_w(const float* __restrict__ W0, const float* __restrict__ W1,
                 const float* __restrict__ W2, const float* __restrict__ W3)
{
    const float* W = (blockIdx.z == 0) ? W0 : (blockIdx.z == 1) ? W1
                   : (blockIdx.z == 2) ? W2 : W3;
    float* Wt = g_WT + (size_t)blockIdx.z * Ddim * Ddim;
    __shared__ float t[32][33];
    const int tx = threadIdx.x, ty = threadIdx.y;
    const int x = blockIdx.x * 32 + tx;
    const int y0 = blockIdx.y * 32;
#pragma unroll
    for (int j = ty; j < 32; j += 8)
        t[j][tx] = W[(size_t)(y0 + j) * Ddim + x];
    __syncthreads();
    const int x2 = y0 + tx;
    const int y2 = blockIdx.x * 32;
#pragma unroll
    for (int j = ty; j < 32; j += 8)
        Wt[(size_t)(y2 + j) * Ddim + x2] = t[tx][j];
}

// ---------------------------------------------------------------------------
// Tensor-core flash attention (causal), tf32 mma.
// CTA: 64 queries x one (b,h); 4 warps x 16 query rows; KV tile = 64 keys.
// K and V^T live in fragment-order smem (uint2 B-frag loads).
// Softmax entirely in C-fragment layout; P -> A-frags via shuffles.
// ---------------------------------------------------------------------------
#define FBLK 66   // words per padded 8x8 fragment block (264 B)

__global__ __launch_bounds__(128)
void attn_tc()
{
    __shared__ uint32_t sK[64 * FBLK];
    __shared__ uint32_t sV[64 * FBLK];

    const int h = blockIdx.y;
    const int b = blockIdx.z;
    const int qt = gridDim.x - 1 - blockIdx.x;   // long CTAs launch first
    const int q0 = qt * 64;

    const int tid = threadIdx.x;
    const int lane = tid & 31;
    const int w = tid >> 5;
    const int r = lane >> 2;
    const int qq = lane & 3;

    const size_t hb = ((size_t)(b * Hn + h) * Sdim) * HDim;
    const float* Qp = g_Q + hb;
    const float* Kp = g_K + hb;
    const float* Vp = g_V + hb;

    // Q fragments (pre-scaled by 1/sqrt(64)*log2(e), tf32-rounded)
    const float SCL = 0.125f * 1.4426950408889634f;
    const int qr_lo = q0 + w * 16 + r;
    uint32_t qf[8][4];
#pragma unroll
    for (int ks = 0; ks < 8; ks++) {
        qf[ks][0] = to_tf32(Qp[(size_t)qr_lo * 64 + ks * 8 + qq] * SCL);
        qf[ks][1] = to_tf32(Qp[(size_t)(qr_lo + 8) * 64 + ks * 8 + qq] * SCL);
        qf[ks][2] = to_tf32(Qp[(size_t)qr_lo * 64 + ks * 8 + qq + 4] * SCL);
        qf[ks][3] = to_tf32(Qp[(size_t)(qr_lo + 8) * 64 + ks * 8 + qq + 4] * SCL);
    }

    float oacc[8][4];
#pragma unroll
    for (int j = 0; j < 8; j++)
#pragma unroll
        for (int e = 0; e < 4; e++) oacc[j][e] = 0.f;
    float m0 = -1e30f, m1 = -1e30f;   // running row maxes (rows r, r+8)
    float l0 = 0.f, l1 = 0.f;         // per-thread partial row sums

    const int s0 = (lane & ~3) | (qq >> 1);   // C-frag -> A-frag source lanes
    const int s1 = s0 + 2;

    for (int k0 = 0; k0 <= q0; k0 += 64) {
        __syncthreads();
        // Load K tile (B-operand frag order) and V tile (transposed frag order)
#pragma unroll
        for (int it = 0; it < 8; it++) {
            int idx = it * 128 + tid;
            int key = idx >> 4;
            int c4 = idx & 15;
            float4 kv = *(const float4*)(Kp + (size_t)(k0 + key) * 64 + c4 * 4);
            int kb = (((key >> 3) * 8 + (c4 >> 1)) * FBLK)
                   + (key & 7) * 8 + (c4 & 1);
            sK[kb + 0] = to_tf32(kv.x);
            sK[kb + 2] = to_tf32(kv.y);
            sK[kb + 4] = to_tf32(kv.z);
            sK[kb + 6] = to_tf32(kv.w);
            float4 vv = *(const float4*)(Vp + (size_t)(k0 + key) * 64 + c4 * 4);
            int vb = (((c4 >> 1) * 8 + (key >> 3)) * FBLK)
                   + (c4 & 1) * 32 + (key & 3) * 2 + ((key >> 2) & 1);
            sV[vb + 0]  = to_tf32(vv.x);
            sV[vb + 8]  = to_tf32(vv.y);
            sV[vb + 16] = to_tf32(vv.z);
            sV[vb + 24] = to_tf32(vv.w);
        }
        __syncthreads();

        // S = Q @ K^T  (per warp: 16 rows x 64 keys)
        float sfr[8][4];
#pragma unroll
        for (int jj = 0; jj < 8; jj++) {
#pragma unroll
            for (int e = 0; e < 4; e++) sfr[jj][e] = 0.f;
#pragma unroll
            for (int ks = 0; ks < 8; ks++) {
                uint2 bf = *(const uint2*)&sK[(jj * 8 + ks) * FBLK + lane * 2];
                mma_tf32(sfr[jj], qf[ks], (const uint32_t*)&bf);
            }
        }

        // Causal mask: only the diagonal tile
        if (k0 == q0) {
            const int qr0 = w * 16 + r, qr1 = qr0 + 8;
#pragma unroll
            for (int jj = 0; jj < 8; jj++) {
                int kc = jj * 8 + qq * 2;
                if (kc > qr0)     sfr[jj][0] = -1e30f;
                if (kc + 1 > qr0) sfr[jj][1] = -1e30f;
                if (kc > qr1)     sfr[jj][2] = -1e30f;
                if (kc + 1 > qr1) sfr[jj][3] = -1e30f;
            }
        }

        // Online softmax (row max via quad bfly; l stays per-thread partial)
        float t0 = -1e30f, t1 = -1e30f;
#pragma unroll
        for (int jj = 0; jj < 8; jj++) {
            t0 = fmaxf(t0, fmaxf(sfr[jj][0], sfr[jj][1]));
            t1 = fmaxf(t1, fmaxf(sfr[jj][2], sfr[jj][3]));
        }
        t0 = fmaxf(t0, __shfl_xor_sync(0xffffffffu, t0, 1));
        t0 = fmaxf(t0, __shfl_xor_sync(0xffffffffu, t0, 2));
        t1 = fmaxf(t1, __shfl_xor_sync(0xffffffffu, t1, 1));
        t1 = fmaxf(t1, __shfl_xor_sync(0xffffffffu, t1, 2));
        const float mn0 = fmaxf(m0, t0), mn1 = fmaxf(m1, t1);
        const float sc0 = ex2(m0 - mn0), sc1 = ex2(m1 - mn1);
        m0 = mn0; m1 = mn1;
        l0 *= sc0; l1 *= sc1;
#pragma unroll
        for (int j = 0; j < 8; j++) {
            oacc[j][0] *= sc0; oacc[j][1] *= sc0;
            oacc[j][2] *= sc1; oacc[j][3] *= sc1;
        }

        uint32_t pf[8][4];
#pragma unroll
        for (int jj = 0; jj < 8; jj++) {
            float p0 = ex2(sfr[jj][0] - m0);
            float p1 = ex2(sfr[jj][1] - m0);
            float p2 = ex2(sfr[jj][2] - m1);
            float p3 = ex2(sfr[jj][3] - m1);
            l0 += p0 + p1;
            l1 += p2 + p3;
            pf[jj][0] = to_tf32(p0);
            pf[jj][1] = to_tf32(p1);
            pf[jj][2] = to_tf32(p2);
            pf[jj][3] = to_tf32(p3);
        }

        // O += P @ V  (A-frags from pf via shuffles)
#pragma unroll
        for (int ks = 0; ks < 8; ks++) {
            uint32_t x00 = __shfl_sync(0xffffffffu, pf[ks][0], s0);
            uint32_t x01 = __shfl_sync(0xffffffffu, pf[ks][1], s0);
            uint32_t x10 = __shfl_sync(0xffffffffu, pf[ks][0], s1);
            uint32_t x11 = __shfl_sync(0xffffffffu, pf[ks][1], s1);
            uint32_t y00 = __shfl_sync(0xffffffffu, pf[ks][2], s0);
            uint32_t y01 = __shfl_sync(0xffffffffu, pf[ks][3], s0);
            uint32_t y10 = __shfl_sync(0xffffffffu, pf[ks][2], s1);
            uint32_t y11 = __shfl_sync(0xffffffffu, pf[ks][3], s1);
            uint32_t a[4];
            a[0] = (lane & 1) ? x01 : x00;
            a[1] = (lane & 1) ? y01 : y00;
            a[2] = (lane & 1) ? x11 : x10;
            a[3] = (lane & 1) ? y11 : y10;
#pragma unroll
            for (int j = 0; j < 8; j++) {
                uint2 bf = *(const uint2*)&sV[(j * 8 + ks) * FBLK + lane * 2];
                mma_tf32(oacc[j], a, (const uint32_t*)&bf);
            }
        }
    }

    // Epilogue: finish row sums, normalize, write ctx
    l0 += __shfl_xor_sync(0xffffffffu, l0, 1);
    l0 += __shfl_xor_sync(0xffffffffu, l0, 2);
    l1 += __shfl_xor_sync(0xffffffffu, l1, 1);
    l1 += __shfl_xor_sync(0xffffffffu, l1, 2);
    const float i0 = 1.f / l0;
    const float i1 = 1.f / l1;

    float* ctx0 = g_ctx + ((size_t)(b * Sdim + qr_lo)) * Ddim + h * 64;
    float* ctx1 = g_ctx + ((size_t)(b * Sdim + qr_lo + 8)) * Ddim + h * 64;
#pragma unroll
    for (int j = 0; j < 8; j++) {
        int col = j * 8 + qq * 2;
        *(float2*)(ctx0 + col) = make_float2(oacc[j][0] * i0, oacc[j][1] * i0);
        *(float2*)(ctx1 + col) = make_float2(oacc[j][2] * i1, oacc[j][3] * i1);
    }
}

// ---------------------------------------------------------------------------
extern "C" void kernel_launch(void* const* d_in, const int* in_sizes, int n_in,
                              void* d_out, int out_size)
{
    const float* x  = (const float*)d_in[0];
    const float* Wq = (const float*)d_in[1];
    const float* Wk = (const float*)d_in[2];
    const float* Wv = (const float*)d_in[3];
    const float* Wo = (const float*)d_in[4];
    const float* bo = (const float*)d_in[5];
    float* out = (float*)d_out;

    cudaFuncSetAttribute(qkv_tc, cudaFuncAttributeMaxDynamicSharedMemorySize, GEMM_SMEM);
    cudaFuncSetAttribute(out_tc, cudaFuncAttributeMaxDynamicSharedMemorySize, GEMM_SMEM);

    dim3 gT(Ddim / 32, Ddim / 32, 4);          // (32, 32, 4)
    transpose_w<<<gT, dim3(32, 8)>>>(Wq, Wk, Wv, Wo);

    dim3 gQKV(Ddim / 128, Mrows / 128, 3);     // (8, 32, 3)
    qkv_tc<<<gQKV, 256, GEMM_SMEM>>>(x);

    dim3 gAttn(Sdim / 64, Hn, Bsz);            // (32, 16, 2)
    attn_tc<<<gAttn, 128>>>();

    dim3 gOut(Ddim / 128, Mrows / 128);        // (8, 32)
    out_tc<<<gOut, 256, GEMM_SMEM>>>(bo, out);
}

// round 6
// speedup vs baseline: 6.0127x; 1.9340x over previous
#include <cuda_runtime.h>
#include <cuda_fp16.h>
#include <cstdint>

// Problem constants
#define Bsz  2
#define Sdim 2048
#define Ddim 1024
#define Hn   16
#define HDim 64
#define Mrows (Bsz * Sdim)   // 4096

// ---------------------------------------------------------------------------
// Device scratch (no cudaMalloc allowed) — fp16 operand storage everywhere
// ---------------------------------------------------------------------------
__device__ __half g_Xh[Mrows * Ddim];            // x in fp16
__device__ __half g_WTh[4 * Ddim * Ddim];        // transposed weights [N][K] fp16
__device__ __half g_Qh[Bsz * Hn * Sdim * HDim];  // [b,h,s,hd] (pre-scaled)
__device__ __half g_Kh[Bsz * Hn * Sdim * HDim];
__device__ __half g_Vh[Bsz * Hn * Sdim * HDim];
__device__ __half g_ctxh[Mrows * Ddim];          // [b*s, d]

// ---------------------------------------------------------------------------
// PTX helpers (sm_80-compatible; compute_103 virtual target — no tcgen05)
// ---------------------------------------------------------------------------
__device__ __forceinline__ float ex2(float x) {
    float r;
    asm("ex2.approx.f32 %0, %1;" : "=f"(r) : "f"(x));
    return r;
}

__device__ __forceinline__ uint32_t packh2(float lo, float hi) {
    uint32_t d;   // cvt.rn.f16x2.f32 d, a, b -> d.hi=cvt(a), d.lo=cvt(b)
    asm("cvt.rn.f16x2.f32 %0, %1, %2;" : "=r"(d) : "f"(hi), "f"(lo));
    return d;
}

__device__ __forceinline__ uint32_t prmt(uint32_t a, uint32_t b, uint32_t s) {
    uint32_t d;
    asm("prmt.b32 %0, %1, %2, %3;" : "=r"(d) : "r"(a), "r"(b), "r"(s));
    return d;
}

__device__ __forceinline__ void mma_f16(float d[4], const uint32_t a[4],
                                        const uint32_t b[2]) {
    asm volatile(
        "mma.sync.aligned.m16n8k16.row.col.f32.f16.f16.f32 "
        "{%0,%1,%2,%3}, {%4,%5,%6,%7}, {%8,%9}, {%0,%1,%2,%3};"
        : "+f"(d[0]), "+f"(d[1]), "+f"(d[2]), "+f"(d[3])
        : "r"(a[0]), "r"(a[1]), "r"(a[2]), "r"(a[3]), "r"(b[0]), "r"(b[1]));
}

// ---------------------------------------------------------------------------
// Projection GEMM fp16: 128x128 CTA tile, 8 warps (2Mx4N), warp tile 64x32,
// K-chunk 32 halves (2 k-steps of 16), double-buffered fragment-order smem.
// ---------------------------------------------------------------------------
#define ABLK 528
#define BBLK 264
#define ABYTES (16 * ABLK)          // 8448
#define BBYTES (32 * BBLK)          // 8448
#define STAGEB (ABYTES + BBYTES)    // 16896
#define NCHUNKS (Ddim / 32)         // 32

__device__ __forceinline__ void run_gemm_f16(
    const __half* __restrict__ Ah, const __half* __restrict__ Bth,
    int m0, int n0, char* smem, float acc[4][4][4])
{
    const int tid = threadIdx.x;
    const int lane = tid & 31;
    const int w = tid >> 5;
    const int wm = w & 1;
    const int wn = w >> 1;

    // Per-thread gmem pointers + smem scatter bases (2 iterations cover tile)
    const __half* agp[2];
    const __half* bgp[2];
    int asa[2], bsa[2];
#pragma unroll
    for (int it = 0; it < 2; it++) {
        int idx = it * 256 + tid;     // 0..511
        int r = idx >> 2;             // row (A) / n (B): 0..127
        int c8 = idx & 3;             // 8-half group within 32-wide chunk
        agp[it] = Ah + (size_t)(m0 + r) * Ddim + c8 * 8;
        asa[it] = ((r >> 4) * 2 + (c8 >> 1)) * ABLK
                + (r & 7) * 64 + (((r >> 3) & 1) + 2 * (c8 & 1)) * 4;
        bgp[it] = Bth + (size_t)(n0 + r) * Ddim + c8 * 8;
        bsa[it] = ABYTES + ((r >> 3) * 2 + (c8 >> 1)) * BBLK
                + (r & 7) * 32 + (c8 & 1) * 4;
    }

    uint4 av[2], bv[2];
#pragma unroll
    for (int it = 0; it < 2; it++) {
        av[it] = *(const uint4*)(agp[it]);
        bv[it] = *(const uint4*)(bgp[it]);
    }
    {
        char* da = smem;
#pragma unroll
        for (int it = 0; it < 2; it++) {
            *(uint32_t*)(da + asa[it] + 0)  = av[it].x;
            *(uint32_t*)(da + asa[it] + 16) = av[it].y;
            *(uint32_t*)(da + asa[it] + 32) = av[it].z;
            *(uint32_t*)(da + asa[it] + 48) = av[it].w;
            *(uint32_t*)(da + bsa[it] + 0)  = bv[it].x;
            *(uint32_t*)(da + bsa[it] + 8)  = bv[it].y;
            *(uint32_t*)(da + bsa[it] + 16) = bv[it].z;
            *(uint32_t*)(da + bsa[it] + 24) = bv[it].w;
        }
    }
    __syncthreads();

    for (int c = 0; c < NCHUNKS; c++) {
        if (c + 1 < NCHUNKS) {
            const int ko = (c + 1) * 32;
#pragma unroll
            for (int it = 0; it < 2; it++) {
                av[it] = *(const uint4*)(agp[it] + ko);
                bv[it] = *(const uint4*)(bgp[it] + ko);
            }
        }
        const char* sa = smem + (size_t)(c & 1) * STAGEB;
        const char* sb = sa + ABYTES;
#pragma unroll
        for (int ks = 0; ks < 2; ks++) {
            uint4 af[4];
            uint2 bf[4];
#pragma unroll
            for (int i = 0; i < 4; i++)
                af[i] = *(const uint4*)(sa + ((wm * 4 + i) * 2 + ks) * ABLK + lane * 16);
#pragma unroll
            for (int j = 0; j < 4; j++)
                bf[j] = *(const uint2*)(sb + ((wn * 4 + j) * 2 + ks) * BBLK + lane * 8);
#pragma unroll
            for (int i = 0; i < 4; i++)
#pragma unroll
                for (int j = 0; j < 4; j++)
                    mma_f16(acc[i][j], (const uint32_t*)&af[i], (const uint32_t*)&bf[j]);
        }
        if (c + 1 < NCHUNKS) {
            char* da = smem + (size_t)((c + 1) & 1) * STAGEB;
#pragma unroll
            for (int it = 0; it < 2; it++) {
                *(uint32_t*)(da + asa[it] + 0)  = av[it].x;
                *(uint32_t*)(da + asa[it] + 16) = av[it].y;
                *(uint32_t*)(da + asa[it] + 32) = av[it].z;
                *(uint32_t*)(da + asa[it] + 48) = av[it].w;
                *(uint32_t*)(da + bsa[it] + 0)  = bv[it].x;
                *(uint32_t*)(da + bsa[it] + 8)  = bv[it].y;
                *(uint32_t*)(da + bsa[it] + 16) = bv[it].z;
                *(uint32_t*)(da + bsa[it] + 24) = bv[it].w;
            }
            __syncthreads();
        }
    }
}

// QKV projections: scatter fp16 results into [B,H,S,HD]; Q pre-scaled.
__global__ __launch_bounds__(256)
void qkv_tc()
{
    __shared__ char smem[2 * STAGEB];
    const int z = blockIdx.z;
    const __half* Bt = g_WTh + (size_t)z * Ddim * Ddim;
    __half* Out = (z == 0) ? g_Qh : (z == 1) ? g_Kh : g_Vh;
    const float scl = (z == 0) ? (0.125f * 1.4426950408889634f) : 1.f;
    const int m0 = blockIdx.y * 128;
    const int n0 = blockIdx.x * 128;

    float acc[4][4][4];
#pragma unroll
    for (int i = 0; i < 4; i++)
#pragma unroll
        for (int j = 0; j < 4; j++)
#pragma unroll
            for (int r = 0; r < 4; r++) acc[i][j][r] = 0.f;

    run_gemm_f16(g_Xh, Bt, m0, n0, smem, acc);

    const int lane = threadIdx.x & 31;
    const int w = threadIdx.x >> 5;
    const int wm = w & 1;
    const int wn = w >> 1;
#pragma unroll
    for (int i = 0; i < 4; i++) {
#pragma unroll
        for (int j = 0; j < 4; j++) {
            const int row = m0 + wm * 64 + i * 16 + (lane >> 2);
            const int col = n0 + wn * 32 + j * 8 + (lane & 3) * 2;
            const int h = col >> 6;
            const int hd = col & 63;
            int b = row >> 11, s = row & 2047;
            *(uint32_t*)(Out + (((size_t)(b * Hn + h) * Sdim + s) << 6) + hd) =
                packh2(acc[i][j][0] * scl, acc[i][j][1] * scl);
            const int r2 = row + 8;
            b = r2 >> 11; s = r2 & 2047;
            *(uint32_t*)(Out + (((size_t)(b * Hn + h) * Sdim + s) << 6) + hd) =
                packh2(acc[i][j][2] * scl, acc[i][j][3] * scl);
        }
    }
}

// Output projection: out = ctx @ Wo^T + bo (fp32 result)
__global__ __launch_bounds__(256)
void out_tc(const float* __restrict__ bo, float* __restrict__ out)
{
    __shared__ char smem[2 * STAGEB];
    const __half* Bt = g_WTh + (size_t)3 * Ddim * Ddim;
    const int m0 = blockIdx.y * 128;
    const int n0 = blockIdx.x * 128;

    float acc[4][4][4];
#pragma unroll
    for (int i = 0; i < 4; i++)
#pragma unroll
        for (int j = 0; j < 4; j++)
#pragma unroll
            for (int r = 0; r < 4; r++) acc[i][j][r] = 0.f;

    run_gemm_f16(g_ctxh, Bt, m0, n0, smem, acc);

    const int lane = threadIdx.x & 31;
    const int w = threadIdx.x >> 5;
    const int wm = w & 1;
    const int wn = w >> 1;
#pragma unroll
    for (int i = 0; i < 4; i++) {
#pragma unroll
        for (int j = 0; j < 4; j++) {
            const int row = m0 + wm * 64 + i * 16 + (lane >> 2);
            const int col = n0 + wn * 32 + j * 8 + (lane & 3) * 2;
            const float2 bb = *(const float2*)(bo + col);
            *(float2*)(out + (size_t)row * Ddim + col) =
                make_float2(acc[i][j][0] + bb.x, acc[i][j][1] + bb.y);
            *(float2*)(out + (size_t)(row + 8) * Ddim + col) =
                make_float2(acc[i][j][2] + bb.x, acc[i][j][3] + bb.y);
        }
    }
}

// ---------------------------------------------------------------------------
// Weight transpose + fp16 convert: g_WTh[z][n][k] = (half)W_z[k][n]
// ---------------------------------------------------------------------------
__global__ __launch_bounds__(256)
void transpose_w(const float* __restrict__ W0, const float* __restrict__ W1,
                 const float* __restrict__ W2, const float* __restrict__ W3)
{
    const float* W = (blockIdx.z == 0) ? W0 : (blockIdx.z == 1) ? W1
                   : (blockIdx.z == 2) ? W2 : W3;
    __half* Wt = g_WTh + (size_t)blockIdx.z * Ddim * Ddim;
    __shared__ float t[32][33];
    const int tx = threadIdx.x, ty = threadIdx.y;
    const int x0 = blockIdx.x * 32;
    const int y0 = blockIdx.y * 32;
#pragma unroll
    for (int j = ty; j < 32; j += 8)
        t[j][tx] = W[(size_t)(y0 + j) * Ddim + x0 + tx];
    __syncthreads();
    const int c = tx & 15;
    const int j = ty + (tx >> 4) * 8;
#pragma unroll
    for (int jo = 0; jo < 32; jo += 16) {
        const int n = x0 + j + jo;
        *(uint32_t*)(Wt + (size_t)n * Ddim + y0 + 2 * c) =
            packh2(t[2 * c][j + jo], t[2 * c + 1][j + jo]);
    }
}

// x -> fp16
__global__ __launch_bounds__(256)
void convert_x(const float* __restrict__ x)
{
    const int idx = blockIdx.x * 256 + threadIdx.x;     // uint4 units of 8 halves
    const float4 a = *(const float4*)(x + (size_t)idx * 8);
    const float4 b = *(const float4*)(x + (size_t)idx * 8 + 4);
    uint4 o;
    o.x = packh2(a.x, a.y);
    o.y = packh2(a.z, a.w);
    o.z = packh2(b.x, b.y);
    o.w = packh2(b.z, b.w);
    ((uint4*)g_Xh)[idx] = o;
}

// ---------------------------------------------------------------------------
// fp16 tensor-core flash attention (causal).
// CTA: 64 queries x one (b,h); 4 warps x 16 rows; KV tile = 64 keys.
// K/V^T in fragment-order smem; P C-frags pack DIRECTLY into PV A-frags.
// ---------------------------------------------------------------------------
#define FW 66   // words per padded fragment block (264 B)

__global__ __launch_bounds__(128)
void attn_tc()
{
    __shared__ uint32_t sK[32 * FW];   // [keytile 0..7][ks 0..3]
    __shared__ uint32_t sV[32 * FW];   // [dtile 0..7][kk 0..3]

    const int h = blockIdx.y;
    const int b = blockIdx.z;
    const int qt = gridDim.x - 1 - blockIdx.x;   // long CTAs first
    const int q0 = qt * 64;

    const int tid = threadIdx.x;
    const int lane = tid & 31;
    const int w = tid >> 5;
    const int r = lane >> 2;
    const int qq = lane & 3;

    const size_t hb = ((size_t)(b * Hn + h) * Sdim) * HDim;
    const __half* Qp = g_Qh + hb;
    const __half* Kp = g_Kh + hb;
    const __half* Vp = g_Vh + hb;

    // Q fragments (already scaled at qkv epilogue): a0..a3 per 16-k step
    const int qr_lo = q0 + w * 16 + r;
    uint32_t qf[4][4];
#pragma unroll
    for (int ks = 0; ks < 4; ks++) {
        qf[ks][0] = *(const uint32_t*)(Qp + (size_t)qr_lo * 64 + ks * 16 + qq * 2);
        qf[ks][1] = *(const uint32_t*)(Qp + (size_t)(qr_lo + 8) * 64 + ks * 16 + qq * 2);
        qf[ks][2] = *(const uint32_t*)(Qp + (size_t)qr_lo * 64 + ks * 16 + 8 + qq * 2);
        qf[ks][3] = *(const uint32_t*)(Qp + (size_t)(qr_lo + 8) * 64 + ks * 16 + 8 + qq * 2);
    }

    float oacc[8][4];
#pragma unroll
    for (int j = 0; j < 8; j++)
#pragma unroll
        for (int e = 0; e < 4; e++) oacc[j][e] = 0.f;
    float m0 = -1e30f, m1 = -1e30f;
    float l0 = 0.f, l1 = 0.f;

    for (int k0 = 0; k0 <= q0; k0 += 64) {
        __syncthreads();
        // K tile: B-frag order. 64 keys x 8 uint4-groups = 512 units (4 iters).
#pragma unroll
        for (int it = 0; it < 4; it++) {
            int idx = it * 128 + tid;
            int key = idx >> 3;           // 0..63
            int c8 = idx & 7;             // 8-half group 0..7 (full 64 dims)
            uint4 ka = *(const uint4*)(Kp + (size_t)(k0 + key) * 64 + c8 * 8);
            int base = ((key >> 3) * 4 + (c8 >> 1)) * FW
                     + (key & 7) * 8 + (c8 & 1);
            sK[base + 0] = ka.x;
            sK[base + 2] = ka.y;
            sK[base + 4] = ka.z;
            sK[base + 6] = ka.w;
        }
        // V tile: transposed (key-pairs packed). 32 kp x 8 groups = 256 (2 iters).
#pragma unroll
        for (int it = 0; it < 2; it++) {
            int idx = it * 128 + tid;
            int kp = idx >> 3;            // key pair 0..31
            int c8 = idx & 7;             // d-group 0..7 (full 64 dims)
            const __half* v0 = Vp + (size_t)(k0 + kp * 2) * 64 + c8 * 8;
            uint4 va = *(const uint4*)(v0);
            uint4 vb = *(const uint4*)(v0 + 64);
            int blk = (c8 * 4 + (kp >> 3)) * FW;
            int reg = (kp >> 2) & 1;
            int lq = kp & 3;
#pragma unroll
            for (int wd = 0; wd < 4; wd++) {
                uint32_t wa = (&va.x)[wd];
                uint32_t wb = (&vb.x)[wd];
                sV[blk + ((2 * wd) * 4 + lq) * 2 + reg]     = prmt(wa, wb, 0x5410);
                sV[blk + ((2 * wd + 1) * 4 + lq) * 2 + reg] = prmt(wa, wb, 0x7632);
            }
        }
        __syncthreads();

        // S = Q @ K^T (16 rows x 64 keys per warp), fp32 accum
        float sfr[8][4];
#pragma unroll
        for (int jj = 0; jj < 8; jj++) {
#pragma unroll
            for (int e = 0; e < 4; e++) sfr[jj][e] = 0.f;
#pragma unroll
            for (int ks = 0; ks < 4; ks++) {
                uint2 bf = *(const uint2*)&sK[(jj * 4 + ks) * FW + lane * 2];
                mma_f16(sfr[jj], qf[ks], (const uint32_t*)&bf);
            }
        }

        // Causal mask (diagonal tile only)
        if (k0 == q0) {
            const int qr0 = w * 16 + r, qr1 = qr0 + 8;
#pragma unroll
            for (int jj = 0; jj < 8; jj++) {
                int kc = jj * 8 + qq * 2;
                if (kc > qr0)     sfr[jj][0] = -1e30f;
                if (kc + 1 > qr0) sfr[jj][1] = -1e30f;
                if (kc > qr1)     sfr[jj][2] = -1e30f;
                if (kc + 1 > qr1) sfr[jj][3] = -1e30f;
            }
        }

        // Online softmax in C-frag layout
        float t0 = -1e30f, t1 = -1e30f;
#pragma unroll
        for (int jj = 0; jj < 8; jj++) {
            t0 = fmaxf(t0, fmaxf(sfr[jj][0], sfr[jj][1]));
            t1 = fmaxf(t1, fmaxf(sfr[jj][2], sfr[jj][3]));
        }
        t0 = fmaxf(t0, __shfl_xor_sync(0xffffffffu, t0, 1));
        t0 = fmaxf(t0, __shfl_xor_sync(0xffffffffu, t0, 2));
        t1 = fmaxf(t1, __shfl_xor_sync(0xffffffffu, t1, 1));
        t1 = fmaxf(t1, __shfl_xor_sync(0xffffffffu, t1, 2));
        const float mn0 = fmaxf(m0, t0), mn1 = fmaxf(m1, t1);
        const float sc0 = ex2(m0 - mn0), sc1 = ex2(m1 - mn1);
        m0 = mn0; m1 = mn1;
        l0 *= sc0; l1 *= sc1;
#pragma unroll
        for (int j = 0; j < 8; j++) {
            oacc[j][0] *= sc0; oacc[j][1] *= sc0;
            oacc[j][2] *= sc1; oacc[j][3] *= sc1;
        }

        // P in fp16 A-frag layout — C-frag pairs pack directly, no shuffles
        uint32_t pf[8][2];
#pragma unroll
        for (int jj = 0; jj < 8; jj++) {
            float p0 = ex2(sfr[jj][0] - m0);
            float p1 = ex2(sfr[jj][1] - m0);
            float p2 = ex2(sfr[jj][2] - m1);
            float p3 = ex2(sfr[jj][3] - m1);
            l0 += p0 + p1;
            l1 += p2 + p3;
            pf[jj][0] = packh2(p0, p1);
            pf[jj][1] = packh2(p2, p3);
        }

        // O += P @ V
#pragma unroll
        for (int kk = 0; kk < 4; kk++) {
            uint32_t a[4];
            a[0] = pf[2 * kk][0];
            a[1] = pf[2 * kk][1];
            a[2] = pf[2 * kk + 1][0];
            a[3] = pf[2 * kk + 1][1];
#pragma unroll
            for (int j = 0; j < 8; j++) {
                uint2 bf = *(const uint2*)&sV[(j * 4 + kk) * FW + lane * 2];
                mma_f16(oacc[j], a, (const uint32_t*)&bf);
            }
        }
    }

    // Reduce row sums, normalize, write fp16 ctx
    l0 += __shfl_xor_sync(0xffffffffu, l0, 1);
    l0 += __shfl_xor_sync(0xffffffffu, l0, 2);
    l1 += __shfl_xor_sync(0xffffffffu, l1, 1);
    l1 += __shfl_xor_sync(0xffffffffu, l1, 2);
    const float i0 = 1.f / l0;
    const float i1 = 1.f / l1;

    __half* ctx0 = g_ctxh + ((size_t)(b * Sdim + qr_lo)) * Ddim + h * 64;
    __half* ctx1 = g_ctxh + ((size_t)(b * Sdim + qr_lo + 8)) * Ddim + h * 64;
#pragma unroll
    for (int j = 0; j < 8; j++) {
        int col = j * 8 + qq * 2;
        *(uint32_t*)(ctx0 + col) = packh2(oacc[j][0] * i0, oacc[j][1] * i0);
        *(uint32_t*)(ctx1 + col) = packh2(oacc[j][2] * i1, oacc[j][3] * i1);
    }
}

// ---------------------------------------------------------------------------
extern "C" void kernel_launch(void* const* d_in, const int* in_sizes, int n_in,
                              void* d_out, int out_size)
{
    const float* x  = (const float*)d_in[0];
    const float* Wq = (const float*)d_in[1];
    const float* Wk = (const float*)d_in[2];
    const float* Wv = (const float*)d_in[3];
    const float* Wo = (const float*)d_in[4];
    const float* bo = (const float*)d_in[5];
    float* out = (float*)d_out;

    convert_x<<<Mrows * Ddim / (256 * 8), 256>>>(x);

    dim3 gT(Ddim / 32, Ddim / 32, 4);          // (32, 32, 4)
    transpose_w<<<gT, dim3(32, 8)>>>(Wq, Wk, Wv, Wo);

    dim3 gQKV(Ddim / 128, Mrows / 128, 3);     // (8, 32, 3)
    qkv_tc<<<gQKV, 256>>>();

    dim3 gAttn(Sdim / 64, Hn, Bsz);            // (32, 16, 2)
    attn_tc<<<gAttn, 128>>>();

    dim3 gOut(Ddim / 128, Mrows / 128);        // (8, 32)
    out_tc<<<gOut, 256>>>(bo, out);
}